// round 9
// baseline (speedup 1.0000x reference)
#include <cuda_runtime.h>
#include <cstdint>
#include <math.h>

#define B_     2
#define L_     1024
#define D_     1024
#define INTER_ 2816
#define S_     32
#define NCH    88

// ---------------- scratch ----------------
__device__ float   g_x2d [(size_t)B_ * INTER_ * L_];   // x_ffn, channel-major
__device__ float   g_xdt [(size_t)B_ * L_ * INTER_];   // deform out, l-major (for GEMM2)
__device__ float   g_ppart[(size_t)B_ * NCH * 7 * L_];
__device__ ushort4 g_tapi[(size_t)B_ * L_ * 9];
__device__ float4  g_tapw[(size_t)B_ * L_ * 9];

// ---------------- helpers (base-target PTX only: sm_80-class) ----------------
__device__ __forceinline__ uint32_t smem_u32(const void* p) {
    uint32_t a;
    asm("{ .reg .u64 t; cvta.to.shared.u64 t, %1; cvt.u32.u64 %0, t; }" : "=r"(a) : "l"(p));
    return a;
}
__device__ __forceinline__ void ldm_x4(uint32_t* r, uint32_t addr) {
    asm volatile("ldmatrix.sync.aligned.m8n8.x4.shared.b16 {%0,%1,%2,%3}, [%4];"
                 : "=r"(r[0]), "=r"(r[1]), "=r"(r[2]), "=r"(r[3]) : "r"(addr));
}
__device__ __forceinline__ void mma_bf16(float* c, const uint32_t* a, const uint32_t* b) {
    asm volatile("mma.sync.aligned.m16n8k16.row.col.f32.bf16.bf16.f32 "
                 "{%0,%1,%2,%3}, {%4,%5,%6,%7}, {%8,%9}, {%0,%1,%2,%3};"
                 : "+f"(c[0]), "+f"(c[1]), "+f"(c[2]), "+f"(c[3])
                 : "r"(a[0]), "r"(a[1]), "r"(a[2]), "r"(a[3]), "r"(b[0]), "r"(b[1]));
}

#define PITCH   80

// ---- GEMM1 stage layout: A_hi[128][40]@0, A_lo@10240, B_hi[128][40]@20480, B_lo@30720
#define G1_ALO  10240u
#define G1_BOFF 20480u
#define G1_BLO  10240u
#define STAGE1  40960
#define SMEM1   (2 * STAGE1)

// ---- GEMM2 stage layout: A_hi[128][40]@0, A_lo@10240, B_hi[64][40]@20480, B_lo@25600
#define G2_ALO  10240u
#define G2_BOFF 20480u
#define G2_BLO  5120u
#define STAGE2  30720
#define SMEM2   (2 * STAGE2)

// convert float4 -> bf16 hi/lo pairs; lo plane at +loOff
__device__ __forceinline__ void cvt_store(char* st, uint32_t off, uint32_t loOff, float4 v) {
    uint32_t h0, h1, l0, l1;
    asm("cvt.rn.bf16x2.f32 %0, %1, %2;" : "=r"(h0) : "f"(v.y), "f"(v.x));
    asm("cvt.rn.bf16x2.f32 %0, %1, %2;" : "=r"(h1) : "f"(v.w), "f"(v.z));
    float r0 = v.x - __uint_as_float(h0 << 16);
    float r1 = v.y - __uint_as_float(h0 & 0xffff0000u);
    float r2 = v.z - __uint_as_float(h1 << 16);
    float r3 = v.w - __uint_as_float(h1 & 0xffff0000u);
    asm("cvt.rn.bf16x2.f32 %0, %1, %2;" : "=r"(l0) : "f"(r1), "f"(r0));
    asm("cvt.rn.bf16x2.f32 %0, %1, %2;" : "=r"(l1) : "f"(r3), "f"(r2));
    *(uint2*)(st + off)         = make_uint2(h0, h1);
    *(uint2*)(st + off + loOff) = make_uint2(l0, l1);
}

// one K-chunk (32) of HMMA: GEMM1 variant (4 Mtiles x 4 Ntiles)
__device__ __forceinline__ void gemm_compute1(uint32_t sb, const int* RB, int wx,
                                              int lane, float acc[4][4][4]) {
    uint32_t laneoff = (uint32_t)((lane & 15) * PITCH + (lane >> 4) * 16);
#pragma unroll
    for (int ks = 0; ks < 2; ks++) {
        uint32_t kb = (uint32_t)ks * 32u;
        uint32_t ah[4][4], al[4][4];
#pragma unroll
        for (int m = 0; m < 4; m++) {
            uint32_t a = sb + (uint32_t)RB[m] * PITCH + laneoff + kb;
            ldm_x4(ah[m], a);
            ldm_x4(al[m], a + G1_ALO);
        }
        uint32_t bh[4][2], bl[4][2];
#pragma unroll
        for (int p = 0; p < 2; p++) {
            uint32_t a = sb + G1_BOFF + (uint32_t)(wx * 32 + p * 16) * PITCH + laneoff + kb;
            uint32_t r[4];
            ldm_x4(r, a);
            bh[2*p][0] = r[0]; bh[2*p+1][0] = r[1]; bh[2*p][1] = r[2]; bh[2*p+1][1] = r[3];
            ldm_x4(r, a + G1_BLO);
            bl[2*p][0] = r[0]; bl[2*p+1][0] = r[1]; bl[2*p][1] = r[2]; bl[2*p+1][1] = r[3];
        }
#pragma unroll
        for (int m = 0; m < 4; m++)
#pragma unroll
            for (int n = 0; n < 4; n++) {
                mma_bf16(acc[m][n], ah[m], bh[n]);
                mma_bf16(acc[m][n], ah[m], bl[n]);
                mma_bf16(acc[m][n], al[m], bh[n]);
            }
    }
}

// GEMM2 variant: 2 Mtiles x 4 Ntiles, B tile 64 rows
__device__ __forceinline__ void gemm_compute2(uint32_t sb, const int* RB, int wx,
                                              int lane, float acc[2][4][4]) {
    uint32_t laneoff = (uint32_t)((lane & 15) * PITCH + (lane >> 4) * 16);
#pragma unroll
    for (int ks = 0; ks < 2; ks++) {
        uint32_t kb = (uint32_t)ks * 32u;
        uint32_t ah[2][4], al[2][4];
#pragma unroll
        for (int m = 0; m < 2; m++) {
            uint32_t a = sb + (uint32_t)RB[m] * PITCH + laneoff + kb;
            ldm_x4(ah[m], a);
            ldm_x4(al[m], a + G2_ALO);
        }
        uint32_t bh[4][2], bl[4][2];
#pragma unroll
        for (int p = 0; p < 2; p++) {
            uint32_t a = sb + G2_BOFF + (uint32_t)(wx * 32 + p * 16) * PITCH + laneoff + kb;
            uint32_t r[4];
            ldm_x4(r, a);
            bh[2*p][0] = r[0]; bh[2*p+1][0] = r[1]; bh[2*p][1] = r[2]; bh[2*p+1][1] = r[3];
            ldm_x4(r, a + G2_BLO);
            bl[2*p][0] = r[0]; bl[2*p+1][0] = r[1]; bl[2*p][1] = r[2]; bl[2*p+1][1] = r[3];
        }
#pragma unroll
        for (int m = 0; m < 2; m++)
#pragma unroll
            for (int n = 0; n < 4; n++) {
                mma_bf16(acc[m][n], ah[m], bh[n]);
                mma_bf16(acc[m][n], ah[m], bl[n]);
                mma_bf16(acc[m][n], al[m], bh[n]);
            }
    }
}

// ================= GEMM1 (mma.sync bf16 3x): gu = x @ wgu^T, fused SiLU ===========
__global__ __launch_bounds__(256, 1) void k_gemm1_mma(const float* __restrict__ x,
                                                      const float* __restrict__ wgu) {
    extern __shared__ char sm[];
    const int t = threadIdx.x, lane = t & 31, wid = t >> 5;
    const int wy = wid >> 2, wx = wid & 3;
    const int b = blockIdx.z, f0 = blockIdx.y * 64, l0 = blockIdx.x * 128;
    const uint32_t sbase = smem_u32(sm);

    const float* gp[8];
    const int c8 = (t & 7) * 4;
#pragma unroll
    for (int p = 0; p < 8; p++) {
        int r = (t >> 3) + (p & 3) * 32;
        if (p < 4) {
            gp[p] = (r < 64) ? wgu + (size_t)(f0 + r) * D_ + c8
                             : wgu + (size_t)(INTER_ + f0 + r - 64) * D_ + c8;
        } else {
            gp[p] = x + ((size_t)b * L_ + l0 + r) * D_ + c8;
        }
    }
    const uint32_t so0 = (uint32_t)((t >> 3) * PITCH + (t & 7) * 8);

    float acc[4][4][4];
#pragma unroll
    for (int m = 0; m < 4; m++)
#pragma unroll
        for (int n = 0; n < 4; n++)
#pragma unroll
            for (int r = 0; r < 4; r++) acc[m][n][r] = 0.f;

    int RB[4] = { wy * 32, wy * 32 + 16, 64 + wy * 32, 64 + wy * 32 + 16 };

    {
#pragma unroll
        for (int p = 0; p < 8; p++) {
            float4 v = *(const float4*)(gp[p]);
            uint32_t off = (uint32_t)((p & 3) * 32 * PITCH) + so0 + ((p < 4) ? 0u : G1_BOFF);
            cvt_store(sm, off, (p < 4) ? G1_ALO : G1_BLO, v);
        }
    }
    __syncthreads();

    const int NC = D_ / 32;
    for (int c = 0; c < NC; c++) {
        int s = c & 1;
        float4 pr[8];
        if (c + 1 < NC) {
#pragma unroll
            for (int p = 0; p < 8; p++) pr[p] = *(const float4*)(gp[p] + (c + 1) * 32);
        }
        gemm_compute1(sbase + (uint32_t)s * STAGE1, RB, wx, lane, acc);
        if (c + 1 < NC) {
            char* st = sm + (s ^ 1) * STAGE1;
#pragma unroll
            for (int p = 0; p < 8; p++) {
                uint32_t off = (uint32_t)((p & 3) * 32 * PITCH) + so0 + ((p < 4) ? 0u : G1_BOFF);
                cvt_store(st, off, (p < 4) ? G1_ALO : G1_BLO, pr[p]);
            }
        }
        __syncthreads();
    }

    const int g = lane >> 2, tg2 = (lane & 3) * 2;
#pragma unroll
    for (int mi = 0; mi < 2; mi++)
#pragma unroll
        for (int ni = 0; ni < 4; ni++)
#pragma unroll
            for (int h = 0; h < 2; h++) {
                float gv0 = acc[mi][ni][h * 2],     gv1 = acc[mi][ni][h * 2 + 1];
                float uv0 = acc[mi + 2][ni][h * 2], uv1 = acc[mi + 2][ni][h * 2 + 1];
                float o0 = uv0 * gv0 / (1.f + expf(-gv0));
                float o1 = uv1 * gv1 / (1.f + expf(-gv1));
                int f = f0 + wy * 32 + mi * 16 + g + h * 8;
                int lc = l0 + wx * 32 + ni * 8 + tg2;
                *(float2*)(g_x2d + ((size_t)b * INTER_ + f) * L_ + lc) = make_float2(o0, o1);
            }
}

// ================= GEMM2 (mma.sync bf16 3x): out[l][d], 128x64 tile ===============
__global__ __launch_bounds__(256, 1) void k_gemm2_mma(const float* __restrict__ wd,
                                                      float* __restrict__ out) {
    extern __shared__ char sm[];
    const int t = threadIdx.x, lane = t & 31, wid = t >> 5;
    const int wy = wid >> 1, wx = wid & 1;
    const int b = blockIdx.z, l0 = blockIdx.y * 128, d0 = blockIdx.x * 64;
    const uint32_t sbase = smem_u32(sm);

    const float* gp[6];
    const int c8 = (t & 7) * 4;
#pragma unroll
    for (int p = 0; p < 6; p++) {
        if (p < 4) {
            int r = (t >> 3) + p * 32;
            gp[p] = g_xdt + ((size_t)b * L_ + l0 + r) * INTER_ + c8;
        } else {
            int r = (t >> 3) + (p - 4) * 32;
            gp[p] = wd + (size_t)(d0 + r) * INTER_ + c8;
        }
    }
    const uint32_t so0 = (uint32_t)((t >> 3) * PITCH + (t & 7) * 8);

    float acc[2][4][4];
#pragma unroll
    for (int m = 0; m < 2; m++)
#pragma unroll
        for (int n = 0; n < 4; n++)
#pragma unroll
            for (int r = 0; r < 4; r++) acc[m][n][r] = 0.f;

    int RB[2] = { wy * 32, wy * 32 + 16 };

    {
#pragma unroll
        for (int p = 0; p < 6; p++) {
            float4 v = *(const float4*)(gp[p]);
            uint32_t off = (p < 4) ? (uint32_t)(p * 32 * PITCH) + so0
                                   : G2_BOFF + (uint32_t)((p - 4) * 32 * PITCH) + so0;
            cvt_store(sm, off, (p < 4) ? G2_ALO : G2_BLO, v);
        }
    }
    __syncthreads();

    const int NC = INTER_ / 32;
    for (int c = 0; c < NC; c++) {
        int s = c & 1;
        float4 pr[6];
        if (c + 1 < NC) {
#pragma unroll
            for (int p = 0; p < 6; p++) pr[p] = *(const float4*)(gp[p] + (c + 1) * 32);
        }
        gemm_compute2(sbase + (uint32_t)s * STAGE2, RB, wx, lane, acc);
        if (c + 1 < NC) {
            char* st = sm + (s ^ 1) * STAGE2;
#pragma unroll
            for (int p = 0; p < 6; p++) {
                uint32_t off = (p < 4) ? (uint32_t)(p * 32 * PITCH) + so0
                                       : G2_BOFF + (uint32_t)((p - 4) * 32 * PITCH) + so0;
                cvt_store(st, off, (p < 4) ? G2_ALO : G2_BLO, pr[p]);
            }
        }
        __syncthreads();
    }

    const int g = lane >> 2, tg2 = (lane & 3) * 2;
#pragma unroll
    for (int mi = 0; mi < 2; mi++)
#pragma unroll
        for (int ni = 0; ni < 4; ni++)
#pragma unroll
            for (int h = 0; h < 2; h++) {
                int l = l0 + wy * 32 + mi * 16 + g + h * 8;
                int d = d0 + wx * 32 + ni * 8 + tg2;
                *(float2*)(out + ((size_t)b * L_ + l) * D_ + d) =
                    make_float2(acc[mi][ni][h * 2], acc[mi][ni][h * 2 + 1]);
            }
}

// ================= Metric conv: pipelined (double-buffer + reg prefetch) ==========
__global__ __launch_bounds__(256) void k_metric(const float* __restrict__ wm) {
    int chunk = blockIdx.x;
    int b = blockIdx.y;
    __shared__ float img[2][1024];
    __shared__ float ws2[32 * 63];
    int t = threadIdx.x;

    // stage all 32 channels' weights once: ws2[ci*63 + o*9 + k]
    for (int idx = t; idx < 32 * 63; idx += 256) {
        int ci = idx / 63, j = idx % 63;
        int o = j / 9, k = j % 9;
        ws2[idx] = wm[((size_t)o * INTER_ + chunk * 32 + ci) * 9 + k];
    }

    float acc[4][7];
#pragma unroll
    for (int j = 0; j < 4; j++)
#pragma unroll
        for (int o = 0; o < 7; o++) acc[j][o] = 0.f;

    const float* src0 = g_x2d + ((size_t)b * INTER_ + chunk * 32) * L_;
    float r0 = src0[t], r1 = src0[256 + t], r2 = src0[512 + t], r3 = src0[768 + t];

    for (int ci = 0; ci < 32; ci++) {
        float* ib = img[ci & 1];
        ib[t] = r0; ib[256 + t] = r1; ib[512 + t] = r2; ib[768 + t] = r3;
        if (ci + 1 < 32) {
            const float* s = src0 + (size_t)(ci + 1) * L_;
            r0 = s[t]; r1 = s[256 + t]; r2 = s[512 + t]; r3 = s[768 + t];
        }
        __syncthreads();
        const float* w = ws2 + ci * 63;
#pragma unroll
        for (int j = 0; j < 4; j++) {
            int pos = j * 256 + t;
            int y = pos >> 5, xx = pos & 31;
            float nb[9];
#pragma unroll
            for (int ky = 0; ky < 3; ky++)
#pragma unroll
                for (int kx = 0; kx < 3; kx++) {
                    int yy = y + ky - 1, xc = xx + kx - 1;
                    nb[ky * 3 + kx] = (yy >= 0 && yy < 32 && xc >= 0 && xc < 32)
                                          ? ib[yy * 32 + xc] : 0.f;
                }
#pragma unroll
            for (int o = 0; o < 7; o++) {
                float s = 0.f;
#pragma unroll
                for (int kk = 0; kk < 9; kk++) s += nb[kk] * w[o * 9 + kk];
                acc[j][o] += s;
            }
        }
    }
#pragma unroll
    for (int j = 0; j < 4; j++)
#pragma unroll
        for (int o = 0; o < 7; o++)
            g_ppart[((size_t)(b * NCH + chunk) * 7 + o) * L_ + j * 256 + t] = acc[j][o];
}

// ================= Fused partial-reduce + tap precompute ==========================
__global__ void k_redtaps(const float* __restrict__ bm) {
    int i = blockIdx.x * 256 + threadIdx.x;
    if (i >= B_ * L_) return;
    int b = i / L_, pos = i % L_;
    int y = pos >> 5, x = pos & 31;

    float pv[7];
#pragma unroll
    for (int o = 0; o < 7; o++) pv[o] = bm[o];
    for (int ch = 0; ch < NCH; ch++) {
        const float* pp = g_ppart + ((size_t)(b * NCH + ch) * 7) * L_ + pos;
#pragma unroll
        for (int o = 0; o < 7; o++) pv[o] += pp[(size_t)o * L_];
    }

    float m00 = pv[0], m01 = pv[1], m10 = pv[2], m11 = pv[3];
    float dry = pv[4], drx = pv[5];
    float sc = tanhf(pv[6]);
#pragma unroll
    for (int k = 0; k < 9; k++) {
        float py = (float)(k / 3 - 1), px = (float)(k % 3 - 1);
        float oy = sc * (m00 * py + m01 * px) + dry;
        float ox = sc * (m10 * py + m11 * px) + drx;
        float posy = (float)y + py + oy;
        float posx = (float)x + px + ox;
        float y0f = floorf(posy), x0f = floorf(posx);
        float ty = posy - y0f, tx = posx - x0f;
        int y0 = (int)y0f, x0 = (int)x0f;
        int y1 = y0 + 1, x1 = x0 + 1;
        float vy0 = (y0 >= 0 && y0 < S_) ? 1.f : 0.f;
        float vy1 = (y1 >= 0 && y1 < S_) ? 1.f : 0.f;
        float vx0 = (x0 >= 0 && x0 < S_) ? 1.f : 0.f;
        float vx1 = (x1 >= 0 && x1 < S_) ? 1.f : 0.f;
        int cy0 = min(max(y0, 0), S_ - 1), cx0 = min(max(x0, 0), S_ - 1);
        int cy1 = min(max(y1, 0), S_ - 1), cx1 = min(max(x1, 0), S_ - 1);
        ushort4 i4;
        i4.x = (unsigned short)(cy0 * S_ + cx0);
        i4.y = (unsigned short)(cy0 * S_ + cx1);
        i4.z = (unsigned short)(cy1 * S_ + cx0);
        i4.w = (unsigned short)(cy1 * S_ + cx1);
        float4 w4;
        w4.x = (1.f - ty) * (1.f - tx) * vy0 * vx0;
        w4.y = (1.f - ty) * tx * vy0 * vx1;
        w4.z = ty * (1.f - tx) * vy1 * vx0;
        w4.w = ty * tx * vy1 * vx1;
        g_tapi[(size_t)i * 9 + k] = i4;
        g_tapw[(size_t)i * 9 + k] = w4;
    }
}

// ================= Deformable depthwise conv: direct l-major output ===============
__global__ __launch_bounds__(256) void k_deform(const float* __restrict__ cw_g,
                                                const float* __restrict__ cb_g) {
    int cg = blockIdx.x;
    int b = blockIdx.y;
    int c0 = cg * 8;
    __shared__ float img[8 * 1024];     // 32 KB
    __shared__ ushort4 ti[576];         // 4.5 KB
    __shared__ float4 tw[576];          // 9 KB
    __shared__ float cw[72];
    __shared__ float obuf[64 * 8];      // 2 KB
    int t = threadIdx.x;

    const float4* src = (const float4*)(g_x2d + ((size_t)b * INTER_ + c0) * L_);
#pragma unroll
    for (int j = 0; j < 8; j++) ((float4*)img)[j * 256 + t] = src[j * 256 + t];
    if (t < 72) cw[t] = cw_g[c0 * 9 + t];

    int lp = t & 63;
    int cl = t >> 6;
    int cA = cl, cB = cl + 4;
    float bA = cb_g[c0 + cA], bB = cb_g[c0 + cB];
    const float* imA = img + cA * 1024;
    const float* imB = img + cB * 1024;

    for (int chunk = 0; chunk < 16; chunk++) {
        __syncthreads();   // prior obuf writes consumed; ti/tw free to overwrite
        for (int e = t; e < 576; e += 256) {
            size_t gi = ((size_t)b * L_ + chunk * 64) * 9 + e;
            ti[e] = g_tapi[gi];
            tw[e] = g_tapw[gi];
        }
        __syncthreads();
        float a0 = bA, a1 = bB;
#pragma unroll
        for (int k = 0; k < 9; k++) {
            int e = lp * 9 + k;
            ushort4 i4 = ti[e];
            float4 w4 = tw[e];
            float s0 = w4.x * imA[i4.x] + w4.y * imA[i4.y] + w4.z * imA[i4.z] + w4.w * imA[i4.w];
            float s1 = w4.x * imB[i4.x] + w4.y * imB[i4.y] + w4.z * imB[i4.z] + w4.w * imB[i4.w];
            a0 += s0 * cw[cA * 9 + k];
            a1 += s1 * cw[cB * 9 + k];
        }
        obuf[lp * 8 + cA] = a0;
        obuf[lp * 8 + cB] = a1;
        __syncthreads();
        // cooperative coalesced write: thread t -> pos t>>2, channel pair (t&3)*2
        {
            int pos = chunk * 64 + (t >> 2);
            int ch = (t & 3) * 2;
            float2 v = *(float2*)&obuf[(t >> 2) * 8 + ch];
            *(float2*)(g_xdt + ((size_t)b * L_ + pos) * INTER_ + c0 + ch) = v;
        }
    }
}

// ================================ launch ==========================================
extern "C" void kernel_launch(void* const* d_in, const int* in_sizes, int n_in,
                              void* d_out, int out_size) {
    const float* x   = (const float*)d_in[0];
    const float* wgu = (const float*)d_in[1];
    const float* wm  = (const float*)d_in[2];
    const float* bm  = (const float*)d_in[3];
    const float* cw  = (const float*)d_in[4];
    const float* cb  = (const float*)d_in[5];
    const float* wd  = (const float*)d_in[6];
    float* out = (float*)d_out;

    cudaFuncSetAttribute(k_gemm1_mma, cudaFuncAttributeMaxDynamicSharedMemorySize, SMEM1);
    cudaFuncSetAttribute(k_gemm2_mma, cudaFuncAttributeMaxDynamicSharedMemorySize, SMEM2);

    k_gemm1_mma<<<dim3(8, 44, 2), 256, SMEM1>>>(x, wgu);
    k_metric<<<dim3(NCH, 2), 256>>>(wm);
    k_redtaps<<<(B_ * L_ + 255) / 256, 256>>>(bm);
    k_deform<<<dim3(INTER_ / 8, 2), 256>>>(cw, cb);
    k_gemm2_mma<<<dim3(D_ / 64, L_ / 128, 2), 256, SMEM2>>>(wd, out);
}

// round 13
// speedup vs baseline: 1.0360x; 1.0360x over previous
#include <cuda_runtime.h>
#include <cstdint>
#include <math.h>

#define B_     2
#define L_     1024
#define D_     1024
#define INTER_ 2816
#define S_     32
#define NCH    88

// ---------------- scratch ----------------
__device__ float   g_x2d [(size_t)B_ * INTER_ * L_];   // x_ffn, channel-major
__device__ float   g_xdt [(size_t)B_ * L_ * INTER_];   // deform out, l-major (for GEMM2)
__device__ float   g_ppart[(size_t)B_ * NCH * 7 * L_];
__device__ ushort4 g_tapi[(size_t)B_ * L_ * 9];
__device__ float4  g_tapw[(size_t)B_ * L_ * 9];

// ---------------- helpers (base-target PTX only: sm_80-class) ----------------
__device__ __forceinline__ uint32_t smem_u32(const void* p) {
    uint32_t a;
    asm("{ .reg .u64 t; cvta.to.shared.u64 t, %1; cvt.u32.u64 %0, t; }" : "=r"(a) : "l"(p));
    return a;
}
__device__ __forceinline__ void ldm_x4(uint32_t* r, uint32_t addr) {
    asm volatile("ldmatrix.sync.aligned.m8n8.x4.shared.b16 {%0,%1,%2,%3}, [%4];"
                 : "=r"(r[0]), "=r"(r[1]), "=r"(r[2]), "=r"(r[3]) : "r"(addr));
}
__device__ __forceinline__ void mma_bf16(float* c, const uint32_t* a, const uint32_t* b) {
    asm volatile("mma.sync.aligned.m16n8k16.row.col.f32.bf16.bf16.f32 "
                 "{%0,%1,%2,%3}, {%4,%5,%6,%7}, {%8,%9}, {%0,%1,%2,%3};"
                 : "+f"(c[0]), "+f"(c[1]), "+f"(c[2]), "+f"(c[3])
                 : "r"(a[0]), "r"(a[1]), "r"(a[2]), "r"(a[3]), "r"(b[0]), "r"(b[1]));
}

#define PITCH   80

// ---- GEMM stage layout: A_hi[128][40]@0, A_lo@10240, B_hi[128][40]@20480, B_lo@30720
#define G1_ALO  10240u
#define G1_BOFF 20480u
#define G1_BLO  10240u
#define STAGE1  40960
#define SMEM1   (2 * STAGE1)

// convert float4 -> bf16 hi/lo pairs; lo plane at +loOff
__device__ __forceinline__ void cvt_store(char* st, uint32_t off, uint32_t loOff, float4 v) {
    uint32_t h0, h1, l0, l1;
    asm("cvt.rn.bf16x2.f32 %0, %1, %2;" : "=r"(h0) : "f"(v.y), "f"(v.x));
    asm("cvt.rn.bf16x2.f32 %0, %1, %2;" : "=r"(h1) : "f"(v.w), "f"(v.z));
    float r0 = v.x - __uint_as_float(h0 << 16);
    float r1 = v.y - __uint_as_float(h0 & 0xffff0000u);
    float r2 = v.z - __uint_as_float(h1 << 16);
    float r3 = v.w - __uint_as_float(h1 & 0xffff0000u);
    asm("cvt.rn.bf16x2.f32 %0, %1, %2;" : "=r"(l0) : "f"(r1), "f"(r0));
    asm("cvt.rn.bf16x2.f32 %0, %1, %2;" : "=r"(l1) : "f"(r3), "f"(r2));
    *(uint2*)(st + off)         = make_uint2(h0, h1);
    *(uint2*)(st + off + loOff) = make_uint2(l0, l1);
}

// one K-chunk (32) of HMMA: 4 Mtiles x 4 Ntiles, 3 split-passes
__device__ __forceinline__ void gemm_compute1(uint32_t sb, const int* RB, int wx,
                                              int lane, float acc[4][4][4]) {
    uint32_t laneoff = (uint32_t)((lane & 15) * PITCH + (lane >> 4) * 16);
#pragma unroll
    for (int ks = 0; ks < 2; ks++) {
        uint32_t kb = (uint32_t)ks * 32u;
        uint32_t ah[4][4], al[4][4];
#pragma unroll
        for (int m = 0; m < 4; m++) {
            uint32_t a = sb + (uint32_t)RB[m] * PITCH + laneoff + kb;
            ldm_x4(ah[m], a);
            ldm_x4(al[m], a + G1_ALO);
        }
        uint32_t bh[4][2], bl[4][2];
#pragma unroll
        for (int p = 0; p < 2; p++) {
            uint32_t a = sb + G1_BOFF + (uint32_t)(wx * 32 + p * 16) * PITCH + laneoff + kb;
            uint32_t r[4];
            ldm_x4(r, a);
            bh[2*p][0] = r[0]; bh[2*p+1][0] = r[1]; bh[2*p][1] = r[2]; bh[2*p+1][1] = r[3];
            ldm_x4(r, a + G1_BLO);
            bl[2*p][0] = r[0]; bl[2*p+1][0] = r[1]; bl[2*p][1] = r[2]; bl[2*p+1][1] = r[3];
        }
#pragma unroll
        for (int m = 0; m < 4; m++)
#pragma unroll
            for (int n = 0; n < 4; n++) {
                mma_bf16(acc[m][n], ah[m], bh[n]);
                mma_bf16(acc[m][n], ah[m], bl[n]);
                mma_bf16(acc[m][n], al[m], bh[n]);
            }
    }
}

// ================= GEMM1 (mma.sync bf16 3x): gu = x @ wgu^T, fused SiLU ===========
__global__ __launch_bounds__(256, 1) void k_gemm1_mma(const float* __restrict__ x,
                                                      const float* __restrict__ wgu) {
    extern __shared__ char sm[];
    const int t = threadIdx.x, lane = t & 31, wid = t >> 5;
    const int wy = wid >> 2, wx = wid & 3;
    const int b = blockIdx.z, f0 = blockIdx.y * 64, l0 = blockIdx.x * 128;
    const uint32_t sbase = smem_u32(sm);

    const float* gp[8];
    const int c8 = (t & 7) * 4;
#pragma unroll
    for (int p = 0; p < 8; p++) {
        int r = (t >> 3) + (p & 3) * 32;
        if (p < 4) {
            gp[p] = (r < 64) ? wgu + (size_t)(f0 + r) * D_ + c8
                             : wgu + (size_t)(INTER_ + f0 + r - 64) * D_ + c8;
        } else {
            gp[p] = x + ((size_t)b * L_ + l0 + r) * D_ + c8;
        }
    }
    const uint32_t so0 = (uint32_t)((t >> 3) * PITCH + (t & 7) * 8);

    float acc[4][4][4];
#pragma unroll
    for (int m = 0; m < 4; m++)
#pragma unroll
        for (int n = 0; n < 4; n++)
#pragma unroll
            for (int r = 0; r < 4; r++) acc[m][n][r] = 0.f;

    int RB[4] = { wy * 32, wy * 32 + 16, 64 + wy * 32, 64 + wy * 32 + 16 };

    {
#pragma unroll
        for (int p = 0; p < 8; p++) {
            float4 v = *(const float4*)(gp[p]);
            uint32_t off = (uint32_t)((p & 3) * 32 * PITCH) + so0 + ((p < 4) ? 0u : G1_BOFF);
            cvt_store(sm, off, (p < 4) ? G1_ALO : G1_BLO, v);
        }
    }
    __syncthreads();

    const int NC = D_ / 32;
    for (int c = 0; c < NC; c++) {
        int s = c & 1;
        float4 pr[8];
        if (c + 1 < NC) {
#pragma unroll
            for (int p = 0; p < 8; p++) pr[p] = *(const float4*)(gp[p] + (c + 1) * 32);
        }
        gemm_compute1(sbase + (uint32_t)s * STAGE1, RB, wx, lane, acc);
        if (c + 1 < NC) {
            char* st = sm + (s ^ 1) * STAGE1;
#pragma unroll
            for (int p = 0; p < 8; p++) {
                uint32_t off = (uint32_t)((p & 3) * 32 * PITCH) + so0 + ((p < 4) ? 0u : G1_BOFF);
                cvt_store(st, off, (p < 4) ? G1_ALO : G1_BLO, pr[p]);
            }
        }
        __syncthreads();
    }

    const int g = lane >> 2, tg2 = (lane & 3) * 2;
#pragma unroll
    for (int mi = 0; mi < 2; mi++)
#pragma unroll
        for (int ni = 0; ni < 4; ni++)
#pragma unroll
            for (int h = 0; h < 2; h++) {
                float gv0 = acc[mi][ni][h * 2],     gv1 = acc[mi][ni][h * 2 + 1];
                float uv0 = acc[mi + 2][ni][h * 2], uv1 = acc[mi + 2][ni][h * 2 + 1];
                float o0 = uv0 * gv0 / (1.f + expf(-gv0));
                float o1 = uv1 * gv1 / (1.f + expf(-gv1));
                int f = f0 + wy * 32 + mi * 16 + g + h * 8;
                int lc = l0 + wx * 32 + ni * 8 + tg2;
                *(float2*)(g_x2d + ((size_t)b * INTER_ + f) * L_ + lc) = make_float2(o0, o1);
            }
}

// ================= GEMM2 (mma.sync bf16 3x): out[l][d], 128x128 tile ==============
__global__ __launch_bounds__(256, 1) void k_gemm2_mma(const float* __restrict__ wd,
                                                      float* __restrict__ out) {
    extern __shared__ char sm[];
    const int t = threadIdx.x, lane = t & 31, wid = t >> 5;
    const int wy = wid >> 2, wx = wid & 3;
    const int b = blockIdx.z, l0 = blockIdx.y * 128, d0 = blockIdx.x * 128;
    const uint32_t sbase = smem_u32(sm);

    const float* gp[8];
    const int c8 = (t & 7) * 4;
#pragma unroll
    for (int p = 0; p < 8; p++) {
        int r = (t >> 3) + (p & 3) * 32;
        if (p < 4) gp[p] = g_xdt + ((size_t)b * L_ + l0 + r) * INTER_ + c8;
        else       gp[p] = wd + (size_t)(d0 + r) * INTER_ + c8;
    }
    const uint32_t so0 = (uint32_t)((t >> 3) * PITCH + (t & 7) * 8);

    float acc[4][4][4];
#pragma unroll
    for (int m = 0; m < 4; m++)
#pragma unroll
        for (int n = 0; n < 4; n++)
#pragma unroll
            for (int r = 0; r < 4; r++) acc[m][n][r] = 0.f;

    int RB[4] = { wy * 64, wy * 64 + 16, wy * 64 + 32, wy * 64 + 48 };

    {
#pragma unroll
        for (int p = 0; p < 8; p++) {
            float4 v = *(const float4*)(gp[p]);
            uint32_t off = (uint32_t)((p & 3) * 32 * PITCH) + so0 + ((p < 4) ? 0u : G1_BOFF);
            cvt_store(sm, off, (p < 4) ? G1_ALO : G1_BLO, v);
        }
    }
    __syncthreads();

    const int NC = INTER_ / 32;
    for (int c = 0; c < NC; c++) {
        int s = c & 1;
        float4 pr[8];
        if (c + 1 < NC) {
#pragma unroll
            for (int p = 0; p < 8; p++) pr[p] = *(const float4*)(gp[p] + (c + 1) * 32);
        }
        gemm_compute1(sbase + (uint32_t)s * STAGE1, RB, wx, lane, acc);
        if (c + 1 < NC) {
            char* st = sm + (s ^ 1) * STAGE1;
#pragma unroll
            for (int p = 0; p < 8; p++) {
                uint32_t off = (uint32_t)((p & 3) * 32 * PITCH) + so0 + ((p < 4) ? 0u : G1_BOFF);
                cvt_store(st, off, (p < 4) ? G1_ALO : G1_BLO, pr[p]);
            }
        }
        __syncthreads();
    }

    const int g = lane >> 2, tg2 = (lane & 3) * 2;
#pragma unroll
    for (int mi = 0; mi < 4; mi++)
#pragma unroll
        for (int ni = 0; ni < 4; ni++)
#pragma unroll
            for (int h = 0; h < 2; h++) {
                int l = l0 + wy * 64 + mi * 16 + g + h * 8;
                int d = d0 + wx * 32 + ni * 8 + tg2;
                *(float2*)(out + ((size_t)b * L_ + l) * D_ + d) =
                    make_float2(acc[mi][ni][h * 2], acc[mi][ni][h * 2 + 1]);
            }
}

// ================= Metric conv: pipelined (double-buffer + reg prefetch) ==========
__global__ __launch_bounds__(256) void k_metric(const float* __restrict__ wm) {
    int chunk = blockIdx.x;
    int b = blockIdx.y;
    __shared__ float img[2][1024];
    __shared__ float ws2[32 * 63];
    int t = threadIdx.x;

    for (int idx = t; idx < 32 * 63; idx += 256) {
        int ci = idx / 63, j = idx % 63;
        int o = j / 9, k = j % 9;
        ws2[idx] = wm[((size_t)o * INTER_ + chunk * 32 + ci) * 9 + k];
    }

    float acc[4][7];
#pragma unroll
    for (int j = 0; j < 4; j++)
#pragma unroll
        for (int o = 0; o < 7; o++) acc[j][o] = 0.f;

    const float* src0 = g_x2d + ((size_t)b * INTER_ + chunk * 32) * L_;
    float r0 = src0[t], r1 = src0[256 + t], r2 = src0[512 + t], r3 = src0[768 + t];

    for (int ci = 0; ci < 32; ci++) {
        float* ib = img[ci & 1];
        ib[t] = r0; ib[256 + t] = r1; ib[512 + t] = r2; ib[768 + t] = r3;
        if (ci + 1 < 32) {
            const float* s = src0 + (size_t)(ci + 1) * L_;
            r0 = s[t]; r1 = s[256 + t]; r2 = s[512 + t]; r3 = s[768 + t];
        }
        __syncthreads();
        const float* w = ws2 + ci * 63;
#pragma unroll
        for (int j = 0; j < 4; j++) {
            int pos = j * 256 + t;
            int y = pos >> 5, xx = pos & 31;
            float nb[9];
#pragma unroll
            for (int ky = 0; ky < 3; ky++)
#pragma unroll
                for (int kx = 0; kx < 3; kx++) {
                    int yy = y + ky - 1, xc = xx + kx - 1;
                    nb[ky * 3 + kx] = (yy >= 0 && yy < 32 && xc >= 0 && xc < 32)
                                          ? ib[yy * 32 + xc] : 0.f;
                }
#pragma unroll
            for (int o = 0; o < 7; o++) {
                float s = 0.f;
#pragma unroll
                for (int kk = 0; kk < 9; kk++) s += nb[kk] * w[o * 9 + kk];
                acc[j][o] += s;
            }
        }
        __syncthreads();
    }
#pragma unroll
    for (int j = 0; j < 4; j++)
#pragma unroll
        for (int o = 0; o < 7; o++)
            g_ppart[((size_t)(b * NCH + chunk) * 7 + o) * L_ + j * 256 + t] = acc[j][o];
}

// ================= Fused partial-reduce + tap precompute ==========================
__global__ void k_redtaps(const float* __restrict__ bm) {
    int i = blockIdx.x * 256 + threadIdx.x;
    if (i >= B_ * L_) return;
    int b = i / L_, pos = i % L_;
    int y = pos >> 5, x = pos & 31;

    float pv[7];
#pragma unroll
    for (int o = 0; o < 7; o++) pv[o] = bm[o];
    for (int ch = 0; ch < NCH; ch++) {
        const float* pp = g_ppart + ((size_t)(b * NCH + ch) * 7) * L_ + pos;
#pragma unroll
        for (int o = 0; o < 7; o++) pv[o] += pp[(size_t)o * L_];
    }

    float m00 = pv[0], m01 = pv[1], m10 = pv[2], m11 = pv[3];
    float dry = pv[4], drx = pv[5];
    float sc = tanhf(pv[6]);
#pragma unroll
    for (int k = 0; k < 9; k++) {
        float py = (float)(k / 3 - 1), px = (float)(k % 3 - 1);
        float oy = sc * (m00 * py + m01 * px) + dry;
        float ox = sc * (m10 * py + m11 * px) + drx;
        float posy = (float)y + py + oy;
        float posx = (float)x + px + ox;
        float y0f = floorf(posy), x0f = floorf(posx);
        float ty = posy - y0f, tx = posx - x0f;
        int y0 = (int)y0f, x0 = (int)x0f;
        int y1 = y0 + 1, x1 = x0 + 1;
        float vy0 = (y0 >= 0 && y0 < S_) ? 1.f : 0.f;
        float vy1 = (y1 >= 0 && y1 < S_) ? 1.f : 0.f;
        float vx0 = (x0 >= 0 && x0 < S_) ? 1.f : 0.f;
        float vx1 = (x1 >= 0 && x1 < S_) ? 1.f : 0.f;
        int cy0 = min(max(y0, 0), S_ - 1), cx0 = min(max(x0, 0), S_ - 1);
        int cy1 = min(max(y1, 0), S_ - 1), cx1 = min(max(x1, 0), S_ - 1);
        ushort4 i4;
        i4.x = (unsigned short)(cy0 * S_ + cx0);
        i4.y = (unsigned short)(cy0 * S_ + cx1);
        i4.z = (unsigned short)(cy1 * S_ + cx0);
        i4.w = (unsigned short)(cy1 * S_ + cx1);
        float4 w4;
        w4.x = (1.f - ty) * (1.f - tx) * vy0 * vx0;
        w4.y = (1.f - ty) * tx * vy0 * vx1;
        w4.z = ty * (1.f - tx) * vy1 * vx0;
        w4.w = ty * tx * vy1 * vx1;
        g_tapi[(size_t)i * 9 + k] = i4;
        g_tapw[(size_t)i * 9 + k] = w4;
    }
}

// ================= Deformable depthwise conv: channel-interleaved gather ==========
// simg[pos][8ch]: one LDS.128 fetches a corner for 4 channels.
#define DF_TI   32768u
#define DF_TW   41984u
#define SMEM_DF 60416
__global__ __launch_bounds__(256) void k_deform(const float* __restrict__ cw_g,
                                                const float* __restrict__ cb_g) {
    extern __shared__ char dsm[];
    float*   simg = (float*)dsm;                 // [1024][8]
    ushort4* ti   = (ushort4*)(dsm + DF_TI);     // [128*9]
    float4*  tw   = (float4*)(dsm + DF_TW);      // [128*9]
    int cg = blockIdx.x, b = blockIdx.y;
    int c0 = cg * 8;
    int t = threadIdx.x;
    int q = t & 1, pi = t >> 1;                  // pi 0..127, q = channel quad

    // load image, transposing channel-major -> [pos][ch]
    {
        const float* src = g_x2d + ((size_t)b * INTER_ + c0) * L_;
        int p0 = t * 4;
#pragma unroll
        for (int j = 0; j < 4; j++) {
            float4 lo, hi;
            lo.x = src[0 * L_ + p0 + j]; lo.y = src[1 * L_ + p0 + j];
            lo.z = src[2 * L_ + p0 + j]; lo.w = src[3 * L_ + p0 + j];
            hi.x = src[4 * L_ + p0 + j]; hi.y = src[5 * L_ + p0 + j];
            hi.z = src[6 * L_ + p0 + j]; hi.w = src[7 * L_ + p0 + j];
            *(float4*)&simg[(p0 + j) * 8]     = lo;
            *(float4*)&simg[(p0 + j) * 8 + 4] = hi;
        }
    }

    // conv weights + bias for this thread's channel quad -> registers
    float4 cwq[9];
    float4 bias;
    {
        int cb4 = c0 + q * 4;
#pragma unroll
        for (int k = 0; k < 9; k++) {
            cwq[k].x = cw_g[(cb4 + 0) * 9 + k];
            cwq[k].y = cw_g[(cb4 + 1) * 9 + k];
            cwq[k].z = cw_g[(cb4 + 2) * 9 + k];
            cwq[k].w = cw_g[(cb4 + 3) * 9 + k];
        }
        bias.x = cb_g[cb4 + 0]; bias.y = cb_g[cb4 + 1];
        bias.z = cb_g[cb4 + 2]; bias.w = cb_g[cb4 + 3];
    }

    for (int chunk = 0; chunk < 8; chunk++) {
        __syncthreads();   // prior gathers done before ti/tw overwrite (also covers simg init)
        for (int e = t; e < 1152; e += 256) {
            size_t gi = ((size_t)b * L_ + chunk * 128) * 9 + e;
            ti[e] = g_tapi[gi];
            tw[e] = g_tapw[gi];
        }
        __syncthreads();
        float4 acc = bias;
#pragma unroll
        for (int k = 0; k < 9; k++) {
            int e = pi * 9 + k;
            ushort4 i4 = ti[e];
            float4  w4 = tw[e];
            const float4 v00 = *(const float4*)&simg[(int)i4.x * 8 + q * 4];
            const float4 v01 = *(const float4*)&simg[(int)i4.y * 8 + q * 4];
            const float4 v10 = *(const float4*)&simg[(int)i4.z * 8 + q * 4];
            const float4 v11 = *(const float4*)&simg[(int)i4.w * 8 + q * 4];
            float sx = w4.x * v00.x + w4.y * v01.x + w4.z * v10.x + w4.w * v11.x;
            float sy = w4.x * v00.y + w4.y * v01.y + w4.z * v10.y + w4.w * v11.y;
            float sz = w4.x * v00.z + w4.y * v01.z + w4.z * v10.z + w4.w * v11.z;
            float sw = w4.x * v00.w + w4.y * v01.w + w4.z * v10.w + w4.w * v11.w;
            acc.x += sx * cwq[k].x;
            acc.y += sy * cwq[k].y;
            acc.z += sz * cwq[k].z;
            acc.w += sw * cwq[k].w;
        }
        int pos = chunk * 128 + pi;
        *(float4*)(g_xdt + ((size_t)b * L_ + pos) * INTER_ + c0 + q * 4) = acc;
    }
}

// ================================ launch ==========================================
extern "C" void kernel_launch(void* const* d_in, const int* in_sizes, int n_in,
                              void* d_out, int out_size) {
    const float* x   = (const float*)d_in[0];
    const float* wgu = (const float*)d_in[1];
    const float* wm  = (const float*)d_in[2];
    const float* bm  = (const float*)d_in[3];
    const float* cw  = (const float*)d_in[4];
    const float* cb  = (const float*)d_in[5];
    const float* wd  = (const float*)d_in[6];
    float* out = (float*)d_out;

    cudaFuncSetAttribute(k_gemm1_mma, cudaFuncAttributeMaxDynamicSharedMemorySize, SMEM1);
    cudaFuncSetAttribute(k_gemm2_mma, cudaFuncAttributeMaxDynamicSharedMemorySize, SMEM1);
    cudaFuncSetAttribute(k_deform,    cudaFuncAttributeMaxDynamicSharedMemorySize, SMEM_DF);

    k_gemm1_mma<<<dim3(8, 44, 2), 256, SMEM1>>>(x, wgu);
    k_metric<<<dim3(NCH, 2), 256>>>(wm);
    k_redtaps<<<(B_ * L_ + 255) / 256, 256>>>(bm);
    k_deform<<<dim3(INTER_ / 8, 2), 256, SMEM_DF>>>(cw, cb);
    k_gemm2_mma<<<dim3(D_ / 128, L_ / 128, 2), 256, SMEM1>>>(wd, out);
}

// round 16
// speedup vs baseline: 1.2241x; 1.1816x over previous
#include <cuda_runtime.h>
#include <cstdint>
#include <math.h>

#define B_     2
#define L_     1024
#define D_     1024
#define INTER_ 2816
#define S_     32
#define NCH    88

// ---------------- scratch ----------------
__device__ float   g_x2d [(size_t)B_ * INTER_ * L_];   // x_ffn, channel-major
__device__ float   g_xdt [(size_t)B_ * L_ * INTER_];   // deform out, l-major (for GEMM2)
__device__ float   g_ppart[(size_t)B_ * NCH * 7 * L_];
__device__ ushort4 g_tapi[(size_t)B_ * L_ * 9];        // idx(10b) | valid(bit15)
__device__ float2  g_tapf[(size_t)B_ * L_ * 9];        // (ty, tx)

// ---------------- helpers (base-target PTX only: sm_80-class) ----------------
__device__ __forceinline__ uint32_t smem_u32(const void* p) {
    uint32_t a;
    asm("{ .reg .u64 t; cvta.to.shared.u64 t, %1; cvt.u32.u64 %0, t; }" : "=r"(a) : "l"(p));
    return a;
}
__device__ __forceinline__ void ldm_x4(uint32_t* r, uint32_t addr) {
    asm volatile("ldmatrix.sync.aligned.m8n8.x4.shared.b16 {%0,%1,%2,%3}, [%4];"
                 : "=r"(r[0]), "=r"(r[1]), "=r"(r[2]), "=r"(r[3]) : "r"(addr));
}
__device__ __forceinline__ void mma_f16(float* c, const uint32_t* a, const uint32_t* b) {
    asm volatile("mma.sync.aligned.m16n8k16.row.col.f32.f16.f16.f32 "
                 "{%0,%1,%2,%3}, {%4,%5,%6,%7}, {%8,%9}, {%0,%1,%2,%3};"
                 : "+f"(c[0]), "+f"(c[1]), "+f"(c[2]), "+f"(c[3])
                 : "r"(a[0]), "r"(a[1]), "r"(a[2]), "r"(a[3]), "r"(b[0]), "r"(b[1]));
}

#define PITCH   80

// ---- GEMM stage layout: A_hi[128][40]@0, A_lo@10240, B_hi[128][40]@20480
#define G_ALO   10240u
#define G_BOFF  20480u
#define STAGE1  30720
#define SMEM1   (2 * STAGE1)

// A operand: fp16 hi plane + fp16 residual plane
__device__ __forceinline__ void cvt_store_a(char* st, uint32_t off, float4 v) {
    uint32_t h0, h1, l0, l1;
    asm("cvt.rn.f16x2.f32 %0, %1, %2;" : "=r"(h0) : "f"(v.y), "f"(v.x));
    asm("cvt.rn.f16x2.f32 %0, %1, %2;" : "=r"(h1) : "f"(v.w), "f"(v.z));
    float a0, a1, a2, a3;
    asm("{.reg .b16 lo,hi; mov.b32 {lo,hi}, %2; cvt.f32.f16 %0, lo; cvt.f32.f16 %1, hi;}"
        : "=f"(a0), "=f"(a1) : "r"(h0));
    asm("{.reg .b16 lo,hi; mov.b32 {lo,hi}, %2; cvt.f32.f16 %0, lo; cvt.f32.f16 %1, hi;}"
        : "=f"(a2), "=f"(a3) : "r"(h1));
    float r0 = v.x - a0, r1 = v.y - a1, r2 = v.z - a2, r3 = v.w - a3;
    asm("cvt.rn.f16x2.f32 %0, %1, %2;" : "=r"(l0) : "f"(r1), "f"(r0));
    asm("cvt.rn.f16x2.f32 %0, %1, %2;" : "=r"(l1) : "f"(r3), "f"(r2));
    *(uint2*)(st + off)         = make_uint2(h0, h1);
    *(uint2*)(st + off + G_ALO) = make_uint2(l0, l1);
}
// B operand: single fp16 rounding
__device__ __forceinline__ void cvt_store_b(char* st, uint32_t off, float4 v) {
    uint32_t h0, h1;
    asm("cvt.rn.f16x2.f32 %0, %1, %2;" : "=r"(h0) : "f"(v.y), "f"(v.x));
    asm("cvt.rn.f16x2.f32 %0, %1, %2;" : "=r"(h1) : "f"(v.w), "f"(v.z));
    *(uint2*)(st + off) = make_uint2(h0, h1);
}

// one K-chunk (32): 2 k16 steps, 4Mx4N tiles, 2 split-passes (ah*bh + al*bh)
__device__ __forceinline__ void gemm_compute1(uint32_t sb, const int* RB, int wx,
                                              int lane, float acc[4][4][4]) {
    uint32_t laneoff = (uint32_t)((lane & 15) * PITCH + (lane >> 4) * 16);
#pragma unroll
    for (int ks = 0; ks < 2; ks++) {
        uint32_t kb = (uint32_t)ks * 32u;
        uint32_t ah[4][4], al[4][4];
#pragma unroll
        for (int m = 0; m < 4; m++) {
            uint32_t a = sb + (uint32_t)RB[m] * PITCH + laneoff + kb;
            ldm_x4(ah[m], a);
            ldm_x4(al[m], a + G_ALO);
        }
        uint32_t bh[4][2];
#pragma unroll
        for (int p = 0; p < 2; p++) {
            uint32_t a = sb + G_BOFF + (uint32_t)(wx * 32 + p * 16) * PITCH + laneoff + kb;
            uint32_t r[4];
            ldm_x4(r, a);
            bh[2*p][0] = r[0]; bh[2*p+1][0] = r[1]; bh[2*p][1] = r[2]; bh[2*p+1][1] = r[3];
        }
#pragma unroll
        for (int m = 0; m < 4; m++)
#pragma unroll
            for (int n = 0; n < 4; n++) {
                mma_f16(acc[m][n], ah[m], bh[n]);
                mma_f16(acc[m][n], al[m], bh[n]);
            }
    }
}

// ================= GEMM1 (fp16 2x): gu = x @ wgu^T, fused SiLU ====================
__global__ __launch_bounds__(256, 1) void k_gemm1_mma(const float* __restrict__ x,
                                                      const float* __restrict__ wgu) {
    extern __shared__ char sm[];
    const int t = threadIdx.x, lane = t & 31, wid = t >> 5;
    const int wy = wid >> 2, wx = wid & 3;
    const int b = blockIdx.z, f0 = blockIdx.y * 64, l0 = blockIdx.x * 128;
    const uint32_t sbase = smem_u32(sm);

    const float* gp[8];
    const int c8 = (t & 7) * 4;
#pragma unroll
    for (int p = 0; p < 8; p++) {
        int r = (t >> 3) + (p & 3) * 32;
        if (p < 4) {
            gp[p] = (r < 64) ? wgu + (size_t)(f0 + r) * D_ + c8
                             : wgu + (size_t)(INTER_ + f0 + r - 64) * D_ + c8;
        } else {
            gp[p] = x + ((size_t)b * L_ + l0 + r) * D_ + c8;
        }
    }
    const uint32_t so0 = (uint32_t)((t >> 3) * PITCH + (t & 7) * 8);

    float acc[4][4][4];
#pragma unroll
    for (int m = 0; m < 4; m++)
#pragma unroll
        for (int n = 0; n < 4; n++)
#pragma unroll
            for (int r = 0; r < 4; r++) acc[m][n][r] = 0.f;

    int RB[4] = { wy * 32, wy * 32 + 16, 64 + wy * 32, 64 + wy * 32 + 16 };

    {
#pragma unroll
        for (int p = 0; p < 8; p++) {
            float4 v = *(const float4*)(gp[p]);
            uint32_t off = (uint32_t)((p & 3) * 32 * PITCH) + so0;
            if (p < 4) cvt_store_a(sm, off, v);
            else       cvt_store_b(sm, off + G_BOFF, v);
        }
    }
    __syncthreads();

    const int NC = D_ / 32;
    for (int c = 0; c < NC; c++) {
        int s = c & 1;
        float4 pr[8];
        if (c + 1 < NC) {
#pragma unroll
            for (int p = 0; p < 8; p++) pr[p] = *(const float4*)(gp[p] + (c + 1) * 32);
        }
        gemm_compute1(sbase + (uint32_t)s * STAGE1, RB, wx, lane, acc);
        if (c + 1 < NC) {
            char* st = sm + (s ^ 1) * STAGE1;
#pragma unroll
            for (int p = 0; p < 8; p++) {
                uint32_t off = (uint32_t)((p & 3) * 32 * PITCH) + so0;
                if (p < 4) cvt_store_a(st, off, pr[p]);
                else       cvt_store_b(st, off + G_BOFF, pr[p]);
            }
        }
        __syncthreads();
    }

    const int g = lane >> 2, tg2 = (lane & 3) * 2;
#pragma unroll
    for (int mi = 0; mi < 2; mi++)
#pragma unroll
        for (int ni = 0; ni < 4; ni++)
#pragma unroll
            for (int h = 0; h < 2; h++) {
                float gv0 = acc[mi][ni][h * 2],     gv1 = acc[mi][ni][h * 2 + 1];
                float uv0 = acc[mi + 2][ni][h * 2], uv1 = acc[mi + 2][ni][h * 2 + 1];
                float o0 = uv0 * gv0 / (1.f + expf(-gv0));
                float o1 = uv1 * gv1 / (1.f + expf(-gv1));
                int f = f0 + wy * 32 + mi * 16 + g + h * 8;
                int lc = l0 + wx * 32 + ni * 8 + tg2;
                *(float2*)(g_x2d + ((size_t)b * INTER_ + f) * L_ + lc) = make_float2(o0, o1);
            }
}

// ================= GEMM2 (fp16 2x): out[l][d], 128x128 tile =======================
__global__ __launch_bounds__(256, 1) void k_gemm2_mma(const float* __restrict__ wd,
                                                      float* __restrict__ out) {
    extern __shared__ char sm[];
    const int t = threadIdx.x, lane = t & 31, wid = t >> 5;
    const int wy = wid >> 2, wx = wid & 3;
    const int b = blockIdx.z, l0 = blockIdx.y * 128, d0 = blockIdx.x * 128;
    const uint32_t sbase = smem_u32(sm);

    const float* gp[8];
    const int c8 = (t & 7) * 4;
#pragma unroll
    for (int p = 0; p < 8; p++) {
        int r = (t >> 3) + (p & 3) * 32;
        if (p < 4) gp[p] = g_xdt + ((size_t)b * L_ + l0 + r) * INTER_ + c8;
        else       gp[p] = wd + (size_t)(d0 + r) * INTER_ + c8;
    }
    const uint32_t so0 = (uint32_t)((t >> 3) * PITCH + (t & 7) * 8);

    float acc[4][4][4];
#pragma unroll
    for (int m = 0; m < 4; m++)
#pragma unroll
        for (int n = 0; n < 4; n++)
#pragma unroll
            for (int r = 0; r < 4; r++) acc[m][n][r] = 0.f;

    int RB[4] = { wy * 64, wy * 64 + 16, wy * 64 + 32, wy * 64 + 48 };

    {
#pragma unroll
        for (int p = 0; p < 8; p++) {
            float4 v = *(const float4*)(gp[p]);
            uint32_t off = (uint32_t)((p & 3) * 32 * PITCH) + so0;
            if (p < 4) cvt_store_a(sm, off, v);
            else       cvt_store_b(sm, off + G_BOFF, v);
        }
    }
    __syncthreads();

    const int NC = INTER_ / 32;
    for (int c = 0; c < NC; c++) {
        int s = c & 1;
        float4 pr[8];
        if (c + 1 < NC) {
#pragma unroll
            for (int p = 0; p < 8; p++) pr[p] = *(const float4*)(gp[p] + (c + 1) * 32);
        }
        gemm_compute1(sbase + (uint32_t)s * STAGE1, RB, wx, lane, acc);
        if (c + 1 < NC) {
            char* st = sm + (s ^ 1) * STAGE1;
#pragma unroll
            for (int p = 0; p < 8; p++) {
                uint32_t off = (uint32_t)((p & 3) * 32 * PITCH) + so0;
                if (p < 4) cvt_store_a(st, off, pr[p]);
                else       cvt_store_b(st, off + G_BOFF, pr[p]);
            }
        }
        __syncthreads();
    }

    const int g = lane >> 2, tg2 = (lane & 3) * 2;
#pragma unroll
    for (int mi = 0; mi < 4; mi++)
#pragma unroll
        for (int ni = 0; ni < 4; ni++)
#pragma unroll
            for (int h = 0; h < 2; h++) {
                int l = l0 + wy * 64 + mi * 16 + g + h * 8;
                int d = d0 + wx * 32 + ni * 8 + tg2;
                *(float2*)(out + ((size_t)b * L_ + l) * D_ + d) =
                    make_float2(acc[mi][ni][h * 2], acc[mi][ni][h * 2 + 1]);
            }
}

// ================= Metric conv: pipelined (double-buffer + reg prefetch) ==========
__global__ __launch_bounds__(256) void k_metric(const float* __restrict__ wm) {
    int chunk = blockIdx.x;
    int b = blockIdx.y;
    __shared__ float img[2][1024];
    __shared__ float ws2[32 * 63];
    int t = threadIdx.x;

    for (int idx = t; idx < 32 * 63; idx += 256) {
        int ci = idx / 63, j = idx % 63;
        int o = j / 9, k = j % 9;
        ws2[idx] = wm[((size_t)o * INTER_ + chunk * 32 + ci) * 9 + k];
    }

    float acc[4][7];
#pragma unroll
    for (int j = 0; j < 4; j++)
#pragma unroll
        for (int o = 0; o < 7; o++) acc[j][o] = 0.f;

    const float* src0 = g_x2d + ((size_t)b * INTER_ + chunk * 32) * L_;
    float r0 = src0[t], r1 = src0[256 + t], r2 = src0[512 + t], r3 = src0[768 + t];

    for (int ci = 0; ci < 32; ci++) {
        float* ib = img[ci & 1];
        ib[t] = r0; ib[256 + t] = r1; ib[512 + t] = r2; ib[768 + t] = r3;
        if (ci + 1 < 32) {
            const float* s = src0 + (size_t)(ci + 1) * L_;
            r0 = s[t]; r1 = s[256 + t]; r2 = s[512 + t]; r3 = s[768 + t];
        }
        __syncthreads();
        const float* w = ws2 + ci * 63;
#pragma unroll
        for (int j = 0; j < 4; j++) {
            int pos = j * 256 + t;
            int y = pos >> 5, xx = pos & 31;
            float nb[9];
#pragma unroll
            for (int ky = 0; ky < 3; ky++)
#pragma unroll
                for (int kx = 0; kx < 3; kx++) {
                    int yy = y + ky - 1, xc = xx + kx - 1;
                    nb[ky * 3 + kx] = (yy >= 0 && yy < 32 && xc >= 0 && xc < 32)
                                          ? ib[yy * 32 + xc] : 0.f;
                }
#pragma unroll
            for (int o = 0; o < 7; o++) {
                float s = 0.f;
#pragma unroll
                for (int kk = 0; kk < 9; kk++) s += nb[kk] * w[o * 9 + kk];
                acc[j][o] += s;
            }
        }
        __syncthreads();
    }
#pragma unroll
    for (int j = 0; j < 4; j++)
#pragma unroll
        for (int o = 0; o < 7; o++)
            g_ppart[((size_t)(b * NCH + chunk) * 7 + o) * L_ + j * 256 + t] = acc[j][o];
}

// ================= Fused partial-reduce + tap precompute ==========================
__global__ void k_redtaps(const float* __restrict__ bm) {
    int i = blockIdx.x * 256 + threadIdx.x;
    if (i >= B_ * L_) return;
    int b = i / L_, pos = i % L_;
    int y = pos >> 5, x = pos & 31;

    float pv[7];
#pragma unroll
    for (int o = 0; o < 7; o++) pv[o] = bm[o];
    for (int ch = 0; ch < NCH; ch++) {
        const float* pp = g_ppart + ((size_t)(b * NCH + ch) * 7) * L_ + pos;
#pragma unroll
        for (int o = 0; o < 7; o++) pv[o] += pp[(size_t)o * L_];
    }

    float m00 = pv[0], m01 = pv[1], m10 = pv[2], m11 = pv[3];
    float dry = pv[4], drx = pv[5];
    float sc = tanhf(pv[6]);
#pragma unroll
    for (int k = 0; k < 9; k++) {
        float py = (float)(k / 3 - 1), px = (float)(k % 3 - 1);
        float oy = sc * (m00 * py + m01 * px) + dry;
        float ox = sc * (m10 * py + m11 * px) + drx;
        float posy = (float)y + py + oy;
        float posx = (float)x + px + ox;
        float y0f = floorf(posy), x0f = floorf(posx);
        float ty = posy - y0f, tx = posx - x0f;
        int y0 = (int)y0f, x0 = (int)x0f;
        int y1 = y0 + 1, x1 = x0 + 1;
        bool by0 = (y0 >= 0 && y0 < S_), by1 = (y1 >= 0 && y1 < S_);
        bool bx0 = (x0 >= 0 && x0 < S_), bx1 = (x1 >= 0 && x1 < S_);
        int cy0 = min(max(y0, 0), S_ - 1), cx0 = min(max(x0, 0), S_ - 1);
        int cy1 = min(max(y1, 0), S_ - 1), cx1 = min(max(x1, 0), S_ - 1);
        ushort4 i4;
        i4.x = (unsigned short)((cy0 * S_ + cx0) | ((by0 && bx0) ? 0x8000 : 0));
        i4.y = (unsigned short)((cy0 * S_ + cx1) | ((by0 && bx1) ? 0x8000 : 0));
        i4.z = (unsigned short)((cy1 * S_ + cx0) | ((by1 && bx0) ? 0x8000 : 0));
        i4.w = (unsigned short)((cy1 * S_ + cx1) | ((by1 && bx1) ? 0x8000 : 0));
        g_tapi[(size_t)i * 9 + k] = i4;
        g_tapf[(size_t)i * 9 + k] = make_float2(ty, tx);
    }
}

// ================= Deformable depthwise conv ======================================
// simg[pos][8ch]; taps as idx+valid (8B) + (ty,tx) (8B); conv weights in smem.
#define DF_TI   32768u
#define DF_TF   41984u
#define DF_CW   51200u
#define SMEM_DF 51488
__global__ __launch_bounds__(256) void k_deform(const float* __restrict__ cw_g,
                                                const float* __restrict__ cb_g) {
    extern __shared__ char dsm[];
    float*   simg = (float*)dsm;                 // [1024][8]
    ushort4* ti   = (ushort4*)(dsm + DF_TI);     // [128*9]
    float2*  tf   = (float2*)(dsm + DF_TF);      // [128*9]
    float*   scw  = (float*)(dsm + DF_CW);       // [9][8] transposed conv weights
    int cg = blockIdx.x, b = blockIdx.y;
    int c0 = cg * 8;
    int t = threadIdx.x;
    int q = t & 1, pi = t >> 1;

    // image load, transposing channel-major -> [pos][ch]
    {
        const float* src = g_x2d + ((size_t)b * INTER_ + c0) * L_;
        int p0 = t * 4;
#pragma unroll
        for (int j = 0; j < 4; j++) {
            float4 lo, hi;
            lo.x = src[0 * L_ + p0 + j]; lo.y = src[1 * L_ + p0 + j];
            lo.z = src[2 * L_ + p0 + j]; lo.w = src[3 * L_ + p0 + j];
            hi.x = src[4 * L_ + p0 + j]; hi.y = src[5 * L_ + p0 + j];
            hi.z = src[6 * L_ + p0 + j]; hi.w = src[7 * L_ + p0 + j];
            *(float4*)&simg[(p0 + j) * 8]     = lo;
            *(float4*)&simg[(p0 + j) * 8 + 4] = hi;
        }
    }
    if (t < 72) scw[t] = cw_g[(c0 + (t & 7)) * 9 + (t >> 3)];

    float4 bias;
    {
        int cb4 = c0 + q * 4;
        bias.x = cb_g[cb4 + 0]; bias.y = cb_g[cb4 + 1];
        bias.z = cb_g[cb4 + 2]; bias.w = cb_g[cb4 + 3];
    }

    for (int chunk = 0; chunk < 8; chunk++) {
        __syncthreads();   // prior gathers done before ti/tf overwrite (also covers init)
        for (int e = t; e < 1152; e += 256) {
            size_t gi = ((size_t)b * L_ + chunk * 128) * 9 + e;
            ti[e] = g_tapi[gi];
            tf[e] = g_tapf[gi];
        }
        __syncthreads();
        float4 acc = bias;
#pragma unroll
        for (int k = 0; k < 9; k++) {
            int e = pi * 9 + k;
            ushort4 i4 = ti[e];
            float2 f2 = tf[e];
            float ty = f2.x, tx = f2.y;
            float uu = 1.f - ty, ss = 1.f - tx;
            float w0 = uu * ss, w1 = uu * tx, w2 = ty * ss, w3 = ty * tx;
            if (!(i4.x & 0x8000)) w0 = 0.f;
            if (!(i4.y & 0x8000)) w1 = 0.f;
            if (!(i4.z & 0x8000)) w2 = 0.f;
            if (!(i4.w & 0x8000)) w3 = 0.f;
            const float4 v00 = *(const float4*)&simg[(int)(i4.x & 0x3ff) * 8 + q * 4];
            const float4 v01 = *(const float4*)&simg[(int)(i4.y & 0x3ff) * 8 + q * 4];
            const float4 v10 = *(const float4*)&simg[(int)(i4.z & 0x3ff) * 8 + q * 4];
            const float4 v11 = *(const float4*)&simg[(int)(i4.w & 0x3ff) * 8 + q * 4];
            const float4 cwk = *(const float4*)&scw[k * 8 + q * 4];
            acc.x += (w0 * v00.x + w1 * v01.x + w2 * v10.x + w3 * v11.x) * cwk.x;
            acc.y += (w0 * v00.y + w1 * v01.y + w2 * v10.y + w3 * v11.y) * cwk.y;
            acc.z += (w0 * v00.z + w1 * v01.z + w2 * v10.z + w3 * v11.z) * cwk.z;
            acc.w += (w0 * v00.w + w1 * v01.w + w2 * v10.w + w3 * v11.w) * cwk.w;
        }
        int pos = chunk * 128 + pi;
        *(float4*)(g_xdt + ((size_t)b * L_ + pos) * INTER_ + c0 + q * 4) = acc;
    }
}

// ================================ launch ==========================================
extern "C" void kernel_launch(void* const* d_in, const int* in_sizes, int n_in,
                              void* d_out, int out_size) {
    const float* x   = (const float*)d_in[0];
    const float* wgu = (const float*)d_in[1];
    const float* wm  = (const float*)d_in[2];
    const float* bm  = (const float*)d_in[3];
    const float* cw  = (const float*)d_in[4];
    const float* cb  = (const float*)d_in[5];
    const float* wd  = (const float*)d_in[6];
    float* out = (float*)d_out;

    cudaFuncSetAttribute(k_gemm1_mma, cudaFuncAttributeMaxDynamicSharedMemorySize, SMEM1);
    cudaFuncSetAttribute(k_gemm2_mma, cudaFuncAttributeMaxDynamicSharedMemorySize, SMEM1);
    cudaFuncSetAttribute(k_deform,    cudaFuncAttributeMaxDynamicSharedMemorySize, SMEM_DF);

    k_gemm1_mma<<<dim3(8, 44, 2), 256, SMEM1>>>(x, wgu);
    k_metric<<<dim3(NCH, 2), 256>>>(wm);
    k_redtaps<<<(B_ * L_ + 255) / 256, 256>>>(bm);
    k_deform<<<dim3(INTER_ / 8, 2), 256, SMEM_DF>>>(cw, cb);
    k_gemm2_mma<<<dim3(D_ / 128, L_ / 128, 2), 256, SMEM1>>>(wd, out);
}